// round 11
// baseline (speedup 1.0000x reference)
#include <cuda_runtime.h>
#include <cuda_bf16.h>
#include <cstdint>

#define NN 50000
#define EE 800000
#define HD 128

// ---------------- scratch (device globals — no allocations allowed) ----------------
__device__ __align__(256) float g_h[NN * HD];     // GEMM output (dinv-scaled)
__device__ __align__(256) float g_buf[NN * HD];   // layer input ping buffer
__device__ __align__(256) __nv_bfloat16 g_wt_hi[3 * HD * HD];  // W^T split hi per layer
__device__ __align__(256) __nv_bfloat16 g_wt_lo[3 * HD * HD];  // W^T split lo per layer
__device__ float g_dinv[NN];
__device__ int   g_cnt[NN];
__device__ int   g_cur[NN];
__device__ int   g_off[NN + 1];
__device__ int   g_csr[EE];
__device__ int   g_is64;

// ---------------- PTX helpers (baseline ISA only: ldmatrix + mma.sync) ----------------

__device__ __forceinline__ uint32_t smem_u32(const void* p) {
    uint32_t a;
    asm("{ .reg .u64 t; cvta.to.shared.u64 t, %1; cvt.u32.u64 %0, t; }" : "=r"(a) : "l"(p));
    return a;
}

__device__ __forceinline__ void ldsm_x4(uint32_t* r, uint32_t addr) {
    asm volatile("ldmatrix.sync.aligned.m8n8.x4.shared.b16 {%0,%1,%2,%3}, [%4];"
                 : "=r"(r[0]), "=r"(r[1]), "=r"(r[2]), "=r"(r[3]) : "r"(addr));
}
__device__ __forceinline__ void ldsm_x2(uint32_t* r, uint32_t addr) {
    asm volatile("ldmatrix.sync.aligned.m8n8.x2.shared.b16 {%0,%1}, [%2];"
                 : "=r"(r[0]), "=r"(r[1]) : "r"(addr));
}
__device__ __forceinline__ void mma_bf16(float* c, const uint32_t* a, const uint32_t* b) {
    asm volatile("mma.sync.aligned.m16n8k16.row.col.f32.bf16.bf16.f32 "
                 "{%0,%1,%2,%3}, {%4,%5,%6,%7}, {%8,%9}, {%0,%1,%2,%3};"
                 : "+f"(c[0]), "+f"(c[1]), "+f"(c[2]), "+f"(c[3])
                 : "r"(a[0]), "r"(a[1]), "r"(a[2]), "r"(a[3]), "r"(b[0]), "r"(b[1]));
}
// pack two floats -> bf16x2 (lo = first arg)
__device__ __forceinline__ uint32_t pk_bf2(float lo, float hi) {
    uint32_t r;
    asm("cvt.rn.bf16x2.f32 %0, %1, %2;" : "=r"(r) : "f"(hi), "f"(lo));
    return r;
}

// Swizzled byte offset inside a 128x32-bf16 tile (64B rows, 16B units):
// unit u ^= (r>>1)&3  -> conflict-free ldmatrix.
__device__ __forceinline__ uint32_t swz_pair(int r, int cp) {   // cp = 2-half pair 0..15
    int u = cp >> 2, w = cp & 3;
    return (uint32_t)(r * 64 + ((u ^ ((r >> 1) & 3)) << 4) + w * 4);
}
__device__ __forceinline__ uint32_t swz_ldsm(int r, int c0) {   // c0 = half col, mult of 8
    int u = c0 >> 3;
    return (uint32_t)(r * 64 + ((u ^ ((r >> 1) & 3)) << 4));
}

// ---------------- dtype detect + init (fused) ----------------

__global__ void k_init(const int* __restrict__ ei32, int n) {
    int i = blockIdx.x * blockDim.x + threadIdx.x;
    if (i < n) { g_cnt[i] = 0; g_cur[i] = 0; }
    if (i == 0) {
        int any = 0;
        for (int j = 0; j < 512; j++) any |= ei32[2 * j + 1];
        g_is64 = (any == 0) ? 1 : 0;
    }
}

__device__ __forceinline__ int edge_at(const void* ei, int pos) {
    if (g_is64) return (int)((const long long*)ei)[pos];
    return ((const int*)ei)[pos];
}

// ---------------- graph preprocessing ----------------

__global__ void k_hist(const void* __restrict__ ei, int e, int n) {
    int i = blockIdx.x * blockDim.x + threadIdx.x;
    if (i < e) {
        int d = edge_at(ei, e + i);
        if ((unsigned)d < (unsigned)n) atomicAdd(&g_cnt[d], 1);
    }
}

// single-block fused scan: counts -> exclusive offsets + dinv (replaces 3 kernels)
__global__ void __launch_bounds__(1024) k_scanall(int n) {
    __shared__ int s[1024];
    int t = threadIdx.x;
    int per = (n + 1023) >> 10;          // elems per thread
    int base = t * per;

    int loc = 0;
    for (int i = 0; i < per; i++) {
        int idx = base + i;
        if (idx < n) loc += g_cnt[idx];
    }
    s[t] = loc;
    __syncthreads();
    for (int d = 1; d < 1024; d <<= 1) {
        int v = (t >= d) ? s[t - d] : 0;
        __syncthreads();
        s[t] += v;
        __syncthreads();
    }
    int run = s[t] - loc;                // exclusive prefix for this thread's range
    for (int i = 0; i < per; i++) {
        int idx = base + i;
        if (idx < n) {
            int c = g_cnt[idx];
            g_off[idx] = run;
            run += c;
            g_dinv[idx] = rsqrtf((float)(c + 1));   // +1 self loop
        }
    }
    if (t == 1023) g_off[n] = s[1023];
}

__global__ void k_scatter(const void* __restrict__ ei, int e, int n) {
    int i = blockIdx.x * blockDim.x + threadIdx.x;
    if (i < e) {
        int s = edge_at(ei, i);
        int d = edge_at(ei, e + i);
        if ((unsigned)s < (unsigned)n && (unsigned)d < (unsigned)n) {
            int p = g_off[d] + atomicAdd(&g_cur[d], 1);
            g_csr[p] = s;
        }
    }
}

// ---------------- W transpose + bf16 hi/lo split (all 3 layers, one launch) ----------------

__global__ void k_wsplit(const float* __restrict__ W1, const float* __restrict__ W2,
                         const float* __restrict__ W3) {
    int layer = blockIdx.x >> 6;                 // 64 blocks per layer
    int idx = (blockIdx.x & 63) * 256 + threadIdx.x;
    const float* W = (layer == 0) ? W1 : (layer == 1) ? W2 : W3;
    int nn = idx & 127, kk = idx >> 7;
    float v = W[kk * HD + nn];
    __nv_bfloat16 h = __float2bfloat16(v);
    __nv_bfloat16 l = __float2bfloat16(v - __bfloat162float(h));
    g_wt_hi[layer * HD * HD + nn * HD + kk] = h;
    g_wt_lo[layer * HD * HD + nn * HD + kk] = l;
}

// ---------------- tensor GEMM: g_h[r] = dinv[r] * (src[r] @ W) ----------------
// 256 threads, CTA tile 128x128, warp grid 4x2 (warp tile 32x64).
// K chunked by 32. 3-term bf16 split via mma.sync m16n8k16.

__global__ void __launch_bounds__(256)
k_gemm_mma(const float* __restrict__ in, int in_is_gbuf, int layer, int n) {
    __shared__ __align__(16) __nv_bfloat16 sA_hi[128 * 32];
    __shared__ __align__(16) __nv_bfloat16 sA_lo[128 * 32];
    __shared__ __align__(16) __nv_bfloat16 sB_hi[128 * 32];
    __shared__ __align__(16) __nv_bfloat16 sB_lo[128 * 32];

    const float* __restrict__ src = in_is_gbuf ? g_buf : in;
    const uint32_t* __restrict__ wh = (const uint32_t*)(g_wt_hi + layer * HD * HD);
    const uint32_t* __restrict__ wl = (const uint32_t*)(g_wt_lo + layer * HD * HD);

    int tid  = threadIdx.x;
    int wid  = tid >> 5;
    int lane = tid & 31;
    int wr   = wid >> 1;
    int wc   = wid & 1;
    int row0 = blockIdx.x * 128;

    uint32_t aHi = smem_u32(sA_hi), aLo = smem_u32(sA_lo);
    uint32_t bHi = smem_u32(sB_hi), bLo = smem_u32(sB_lo);

    float acc[2][8][4];
#pragma unroll
    for (int mt = 0; mt < 2; mt++)
#pragma unroll
        for (int nt = 0; nt < 8; nt++)
#pragma unroll
            for (int q = 0; q < 4; q++) acc[mt][nt][q] = 0.f;

    for (int kc = 0; kc < 4; kc++) {
        if (kc) __syncthreads();

        // stage A: 2048 bf16x2 pairs, split fp32 -> hi/lo on the fly
#pragma unroll
        for (int it = 0; it < 8; it++) {
            int p = tid + it * 256;
            int r = p >> 4, cp = p & 15;
            int gr = row0 + r;
            float v0 = 0.f, v1 = 0.f;
            if (gr < n) {
                const float* rp = &src[gr * HD + kc * 32 + cp * 2];
                v0 = rp[0]; v1 = rp[1];
            }
            float h0 = __bfloat162float(__float2bfloat16(v0));
            float h1 = __bfloat162float(__float2bfloat16(v1));
            uint32_t off = swz_pair(r, cp);
            *(uint32_t*)((char*)sA_hi + off) = pk_bf2(v0, v1);
            *(uint32_t*)((char*)sA_lo + off) = pk_bf2(v0 - h0, v1 - h1);
            *(uint32_t*)((char*)sB_hi + off) = wh[r * 64 + kc * 16 + cp];
            *(uint32_t*)((char*)sB_lo + off) = wl[r * 64 + kc * 16 + cp];
        }
        __syncthreads();

#pragma unroll
        for (int ks = 0; ks < 2; ks++) {
            int k0 = ks * 16;
            uint32_t ah[2][4], al[2][4];
#pragma unroll
            for (int mt = 0; mt < 2; mt++) {
                int r = wr * 32 + mt * 16 + (lane & 15);
                int c0 = k0 + (lane >> 4) * 8;
                uint32_t off = swz_ldsm(r, c0);
                ldsm_x4(ah[mt], aHi + off);
                ldsm_x4(al[mt], aLo + off);
            }
#pragma unroll
            for (int nt = 0; nt < 8; nt++) {
                int r = wc * 64 + nt * 8 + (lane & 7);
                int c0 = k0 + ((lane >> 3) & 1) * 8;
                uint32_t off = swz_ldsm(r, c0);
                uint32_t bh[2], bl[2];
                ldsm_x2(bh, bHi + off);
                ldsm_x2(bl, bLo + off);
#pragma unroll
                for (int mt = 0; mt < 2; mt++) {
                    mma_bf16(acc[mt][nt], ah[mt], bh);
                    mma_bf16(acc[mt][nt], ah[mt], bl);
                    mma_bf16(acc[mt][nt], al[mt], bh);
                }
            }
        }
    }

    // epilogue
#pragma unroll
    for (int mt = 0; mt < 2; mt++) {
        int r1 = row0 + wr * 32 + mt * 16 + (lane >> 2);
        int r2 = r1 + 8;
        float dv1 = (r1 < n) ? g_dinv[r1] : 0.f;
        float dv2 = (r2 < n) ? g_dinv[r2] : 0.f;
#pragma unroll
        for (int nt = 0; nt < 8; nt++) {
            int col = wc * 64 + nt * 8 + (lane & 3) * 2;
            if (r1 < n) {
                float2 o = make_float2(acc[mt][nt][0] * dv1, acc[mt][nt][1] * dv1);
                *(float2*)&g_h[r1 * HD + col] = o;
            }
            if (r2 < n) {
                float2 o = make_float2(acc[mt][nt][2] * dv2, acc[mt][nt][3] * dv2);
                *(float2*)&g_h[r2 * HD + col] = o;
            }
        }
    }
}

// ---------------- Aggregation: warp per node, register accumulators (R8-proven) ----------------

__global__ void k_agg(const float* __restrict__ bias, float* __restrict__ out,
                      int out_is_gbuf, int n, int do_relu) {
    int w = (blockIdx.x * blockDim.x + threadIdx.x) >> 5;
    int lane = threadIdx.x & 31;
    if (w >= n) return;

    float* __restrict__ dst = out_is_gbuf ? g_buf : out;

    const float4* hv = (const float4*)g_h;
    float4 a0 = hv[w * 32 + lane];               // self loop
    float4 a1 = make_float4(0.f, 0.f, 0.f, 0.f);
    float4 a2 = make_float4(0.f, 0.f, 0.f, 0.f);
    float4 a3 = make_float4(0.f, 0.f, 0.f, 0.f);

    int beg = g_off[w], end = g_off[w + 1];
    int j = beg;
    for (; j + 3 < end; j += 4) {
        int s0 = g_csr[j], s1 = g_csr[j + 1], s2 = g_csr[j + 2], s3 = g_csr[j + 3];
        float4 m0 = hv[s0 * 32 + lane];
        float4 m1 = hv[s1 * 32 + lane];
        float4 m2 = hv[s2 * 32 + lane];
        float4 m3 = hv[s3 * 32 + lane];
        a0.x += m0.x; a0.y += m0.y; a0.z += m0.z; a0.w += m0.w;
        a1.x += m1.x; a1.y += m1.y; a1.z += m1.z; a1.w += m1.w;
        a2.x += m2.x; a2.y += m2.y; a2.z += m2.z; a2.w += m2.w;
        a3.x += m3.x; a3.y += m3.y; a3.z += m3.z; a3.w += m3.w;
    }
    for (; j < end; j++) {
        float4 m = hv[g_csr[j] * 32 + lane];
        a0.x += m.x; a0.y += m.y; a0.z += m.z; a0.w += m.w;
    }
    float4 acc;
    acc.x = (a0.x + a1.x) + (a2.x + a3.x);
    acc.y = (a0.y + a1.y) + (a2.y + a3.y);
    acc.z = (a0.z + a1.z) + (a2.z + a3.z);
    acc.w = (a0.w + a1.w) + (a2.w + a3.w);

    float dv = g_dinv[w];
    float4 bb = ((const float4*)bias)[lane];
    acc.x = fmaf(acc.x, dv, bb.x);
    acc.y = fmaf(acc.y, dv, bb.y);
    acc.z = fmaf(acc.z, dv, bb.z);
    acc.w = fmaf(acc.w, dv, bb.w);
    if (do_relu) {
        acc.x = fmaxf(acc.x, 0.f); acc.y = fmaxf(acc.y, 0.f);
        acc.z = fmaxf(acc.z, 0.f); acc.w = fmaxf(acc.w, 0.f);
    }
    ((float4*)dst)[w * 32 + lane] = acc;
}

// ---------------- launch ----------------

extern "C" void kernel_launch(void* const* d_in, const int* in_sizes, int n_in,
                              void* d_out, int out_size) {
    const float* x  = (const float*)d_in[0];
    const void*  ei = d_in[1];
    const float* W1 = (const float*)d_in[2];
    const float* b1 = (const float*)d_in[3];
    const float* W2 = (const float*)d_in[4];
    const float* b2 = (const float*)d_in[5];
    const float* W3 = (const float*)d_in[6];
    const float* b3 = (const float*)d_in[7];
    float* out = (float*)d_out;

    int n = in_sizes[0] / HD;     // 50000
    int e = in_sizes[1] / 2;      // 800000

    k_init<<<(n + 255) / 256, 256>>>((const int*)ei, n);
    k_hist<<<(e + 255) / 256, 256>>>(ei, e, n);
    k_scanall<<<1, 1024>>>(n);
    k_scatter<<<(e + 255) / 256, 256>>>(ei, e, n);
    k_wsplit<<<192, 256>>>(W1, W2, W3);

    int gemm_blocks = (n + 127) / 128;
    int agg_blocks  = (n * 32 + 255) / 256;

    // layer 1: x -> g_h -> g_buf (relu)
    k_gemm_mma<<<gemm_blocks, 256>>>(x, 0, 0, n);
    k_agg     <<<agg_blocks, 256>>>(b1, nullptr, 1, n, 1);
    // layer 2: g_buf -> g_h -> g_buf (relu)
    k_gemm_mma<<<gemm_blocks, 256>>>(nullptr, 1, 1, n);
    k_agg     <<<agg_blocks, 256>>>(b2, nullptr, 1, n, 1);
    // layer 3: g_buf -> g_h -> out
    k_gemm_mma<<<gemm_blocks, 256>>>(nullptr, 1, 2, n);
    k_agg     <<<agg_blocks, 256>>>(b3, out, 0, n, 0);
}

// round 13
// speedup vs baseline: 1.3506x; 1.3506x over previous
#include <cuda_runtime.h>
#include <cuda_bf16.h>
#include <cstdint>

#define NN 50000
#define EE 800000
#define HD 128

// ---------------- scratch (device globals — no allocations allowed) ----------------
__device__ __align__(256) float g_h[NN * HD];     // GEMM output (dinv-scaled)
__device__ __align__(256) float g_buf[NN * HD];   // layer input ping buffer
__device__ __align__(256) __nv_bfloat16 g_wt_hi[3 * HD * HD];  // W^T split hi per layer
__device__ __align__(256) __nv_bfloat16 g_wt_lo[3 * HD * HD];  // W^T split lo per layer
__device__ float g_dinv[NN];
__device__ int   g_cnt[NN];
__device__ int   g_cur[NN];
__device__ int   g_off[NN + 1];
__device__ int   g_csr[EE];
__device__ int   g_bsum[64];
__device__ int   g_boff[64];
__device__ int   g_is64;

// ---------------- PTX helpers (baseline ISA only: ldmatrix + mma.sync) ----------------

__device__ __forceinline__ uint32_t smem_u32(const void* p) {
    uint32_t a;
    asm("{ .reg .u64 t; cvta.to.shared.u64 t, %1; cvt.u32.u64 %0, t; }" : "=r"(a) : "l"(p));
    return a;
}

__device__ __forceinline__ void ldsm_x4(uint32_t* r, uint32_t addr) {
    asm volatile("ldmatrix.sync.aligned.m8n8.x4.shared.b16 {%0,%1,%2,%3}, [%4];"
                 : "=r"(r[0]), "=r"(r[1]), "=r"(r[2]), "=r"(r[3]) : "r"(addr));
}
__device__ __forceinline__ void ldsm_x2(uint32_t* r, uint32_t addr) {
    asm volatile("ldmatrix.sync.aligned.m8n8.x2.shared.b16 {%0,%1}, [%2];"
                 : "=r"(r[0]), "=r"(r[1]) : "r"(addr));
}
__device__ __forceinline__ void mma_bf16(float* c, const uint32_t* a, const uint32_t* b) {
    asm volatile("mma.sync.aligned.m16n8k16.row.col.f32.bf16.bf16.f32 "
                 "{%0,%1,%2,%3}, {%4,%5,%6,%7}, {%8,%9}, {%0,%1,%2,%3};"
                 : "+f"(c[0]), "+f"(c[1]), "+f"(c[2]), "+f"(c[3])
                 : "r"(a[0]), "r"(a[1]), "r"(a[2]), "r"(a[3]), "r"(b[0]), "r"(b[1]));
}
// pack two floats -> bf16x2 (lo = first arg)
__device__ __forceinline__ uint32_t pk_bf2(float lo, float hi) {
    uint32_t r;
    asm("cvt.rn.bf16x2.f32 %0, %1, %2;" : "=r"(r) : "f"(hi), "f"(lo));
    return r;
}

// Swizzled byte offset inside a 128x32-bf16 tile (64B rows, 16B units):
// unit u ^= (r>>1)&3  -> conflict-free ldmatrix.
__device__ __forceinline__ uint32_t swz_pair(int r, int cp) {   // cp = 2-half pair 0..15
    int u = cp >> 2, w = cp & 3;
    return (uint32_t)(r * 64 + ((u ^ ((r >> 1) & 3)) << 4) + w * 4);
}
__device__ __forceinline__ uint32_t swz_ldsm(int r, int c0) {   // c0 = half col, mult of 8
    int u = c0 >> 3;
    return (uint32_t)(r * 64 + ((u ^ ((r >> 1) & 3)) << 4));
}

// ---------------- dtype detect + init (fused) ----------------

__global__ void k_init(const int* __restrict__ ei32, int n) {
    int i = blockIdx.x * blockDim.x + threadIdx.x;
    if (i < n) { g_cnt[i] = 0; g_cur[i] = 0; }
    if (i == 0) {
        int any = 0;
        for (int j = 0; j < 512; j++) any |= ei32[2 * j + 1];
        g_is64 = (any == 0) ? 1 : 0;
    }
}

__device__ __forceinline__ int edge_at(const void* ei, int pos) {
    if (g_is64) return (int)((const long long*)ei)[pos];
    return ((const int*)ei)[pos];
}

// ---------------- graph preprocessing ----------------
// hist/scatter: 4 edges per thread -> 4-8 independent loads in flight
// (ncu: issue 5.8%, occ 82% = latency-bound at MLP~2).

__global__ void k_hist(const void* __restrict__ ei, int e, int n) {
    int i0 = (blockIdx.x * blockDim.x + threadIdx.x) * 4;
    int d[4];
#pragma unroll
    for (int k = 0; k < 4; k++) {
        int i = i0 + k;
        d[k] = (i < e) ? edge_at(ei, e + i) : -1;
    }
#pragma unroll
    for (int k = 0; k < 4; k++)
        if ((unsigned)d[k] < (unsigned)n) atomicAdd(&g_cnt[d[k]], 1);
}

__global__ void k_scan1(int n) {
    __shared__ int s[1024];
    int i = blockIdx.x * 1024 + threadIdx.x;
    int v = (i < n) ? g_cnt[i] : 0;
    s[threadIdx.x] = v;
    __syncthreads();
    for (int d = 1; d < 1024; d <<= 1) {
        int t = (threadIdx.x >= (unsigned)d) ? s[threadIdx.x - d] : 0;
        __syncthreads();
        s[threadIdx.x] += t;
        __syncthreads();
    }
    if (i < n) g_off[i] = s[threadIdx.x] - v;          // exclusive
    if (threadIdx.x == 1023) g_bsum[blockIdx.x] = s[1023];
}

__global__ void k_scan2(int nb, int n) {
    __shared__ int s[1024];
    int v = (threadIdx.x < (unsigned)nb) ? g_bsum[threadIdx.x] : 0;
    s[threadIdx.x] = v;
    __syncthreads();
    for (int d = 1; d < 1024; d <<= 1) {
        int t = (threadIdx.x >= (unsigned)d) ? s[threadIdx.x - d] : 0;
        __syncthreads();
        s[threadIdx.x] += t;
        __syncthreads();
    }
    if (threadIdx.x < (unsigned)nb) g_boff[threadIdx.x] = s[threadIdx.x] - v;
    if (threadIdx.x == 1023) g_off[n] = s[1023];       // total = E
}

// scan fixup + dinv fused
__global__ void k_scan3(int n) {
    int i = blockIdx.x * 1024 + threadIdx.x;
    if (i < n) {
        g_off[i] += g_boff[blockIdx.x];
        g_dinv[i] = rsqrtf((float)(g_cnt[i] + 1));     // +1 self loop
    }
}

__global__ void k_scatter(const void* __restrict__ ei, int e, int n) {
    int i0 = (blockIdx.x * blockDim.x + threadIdx.x) * 4;
    int s[4], d[4];
#pragma unroll
    for (int k = 0; k < 4; k++) {
        int i = i0 + k;
        if (i < e) { s[k] = edge_at(ei, i); d[k] = edge_at(ei, e + i); }
        else       { s[k] = -1; d[k] = -1; }
    }
#pragma unroll
    for (int k = 0; k < 4; k++) {
        if ((unsigned)s[k] < (unsigned)n && (unsigned)d[k] < (unsigned)n) {
            int p = g_off[d[k]] + atomicAdd(&g_cur[d[k]], 1);
            g_csr[p] = s[k];
        }
    }
}

// ---------------- W transpose + bf16 hi/lo split (all 3 layers, one launch) ----------------

__global__ void k_wsplit(const float* __restrict__ W1, const float* __restrict__ W2,
                         const float* __restrict__ W3) {
    int layer = blockIdx.x >> 6;                 // 64 blocks per layer
    int idx = (blockIdx.x & 63) * 256 + threadIdx.x;
    const float* W = (layer == 0) ? W1 : (layer == 1) ? W2 : W3;
    int nn = idx & 127, kk = idx >> 7;
    float v = W[kk * HD + nn];
    __nv_bfloat16 h = __float2bfloat16(v);
    __nv_bfloat16 l = __float2bfloat16(v - __bfloat162float(h));
    g_wt_hi[layer * HD * HD + nn * HD + kk] = h;
    g_wt_lo[layer * HD * HD + nn * HD + kk] = l;
}

// ---------------- tensor GEMM: g_h[r] = dinv[r] * (src[r] @ W) ----------------
// 256 threads, CTA tile 128x128, warp grid 4x2 (warp tile 32x64).
// K chunked by 32. 3-term bf16 split via mma.sync m16n8k16. (R8-proven)

__global__ void __launch_bounds__(256)
k_gemm_mma(const float* __restrict__ in, int in_is_gbuf, int layer, int n) {
    __shared__ __align__(16) __nv_bfloat16 sA_hi[128 * 32];
    __shared__ __align__(16) __nv_bfloat16 sA_lo[128 * 32];
    __shared__ __align__(16) __nv_bfloat16 sB_hi[128 * 32];
    __shared__ __align__(16) __nv_bfloat16 sB_lo[128 * 32];

    const float* __restrict__ src = in_is_gbuf ? g_buf : in;
    const uint32_t* __restrict__ wh = (const uint32_t*)(g_wt_hi + layer * HD * HD);
    const uint32_t* __restrict__ wl = (const uint32_t*)(g_wt_lo + layer * HD * HD);

    int tid  = threadIdx.x;
    int wid  = tid >> 5;
    int lane = tid & 31;
    int wr   = wid >> 1;
    int wc   = wid & 1;
    int row0 = blockIdx.x * 128;

    uint32_t aHi = smem_u32(sA_hi), aLo = smem_u32(sA_lo);
    uint32_t bHi = smem_u32(sB_hi), bLo = smem_u32(sB_lo);

    float acc[2][8][4];
#pragma unroll
    for (int mt = 0; mt < 2; mt++)
#pragma unroll
        for (int nt = 0; nt < 8; nt++)
#pragma unroll
            for (int q = 0; q < 4; q++) acc[mt][nt][q] = 0.f;

    for (int kc = 0; kc < 4; kc++) {
        if (kc) __syncthreads();

        // stage A: 2048 bf16x2 pairs, split fp32 -> hi/lo on the fly
#pragma unroll
        for (int it = 0; it < 8; it++) {
            int p = tid + it * 256;
            int r = p >> 4, cp = p & 15;
            int gr = row0 + r;
            float v0 = 0.f, v1 = 0.f;
            if (gr < n) {
                const float* rp = &src[gr * HD + kc * 32 + cp * 2];
                v0 = rp[0]; v1 = rp[1];
            }
            float h0 = __bfloat162float(__float2bfloat16(v0));
            float h1 = __bfloat162float(__float2bfloat16(v1));
            uint32_t off = swz_pair(r, cp);
            *(uint32_t*)((char*)sA_hi + off) = pk_bf2(v0, v1);
            *(uint32_t*)((char*)sA_lo + off) = pk_bf2(v0 - h0, v1 - h1);
            *(uint32_t*)((char*)sB_hi + off) = wh[r * 64 + kc * 16 + cp];
            *(uint32_t*)((char*)sB_lo + off) = wl[r * 64 + kc * 16 + cp];
        }
        __syncthreads();

#pragma unroll
        for (int ks = 0; ks < 2; ks++) {
            int k0 = ks * 16;
            uint32_t ah[2][4], al[2][4];
#pragma unroll
            for (int mt = 0; mt < 2; mt++) {
                int r = wr * 32 + mt * 16 + (lane & 15);
                int c0 = k0 + (lane >> 4) * 8;
                uint32_t off = swz_ldsm(r, c0);
                ldsm_x4(ah[mt], aHi + off);
                ldsm_x4(al[mt], aLo + off);
            }
#pragma unroll
            for (int nt = 0; nt < 8; nt++) {
                int r = wc * 64 + nt * 8 + (lane & 7);
                int c0 = k0 + ((lane >> 3) & 1) * 8;
                uint32_t off = swz_ldsm(r, c0);
                uint32_t bh[2], bl[2];
                ldsm_x2(bh, bHi + off);
                ldsm_x2(bl, bLo + off);
#pragma unroll
                for (int mt = 0; mt < 2; mt++) {
                    mma_bf16(acc[mt][nt], ah[mt], bh);
                    mma_bf16(acc[mt][nt], ah[mt], bl);
                    mma_bf16(acc[mt][nt], al[mt], bh);
                }
            }
        }
    }

    // epilogue
#pragma unroll
    for (int mt = 0; mt < 2; mt++) {
        int r1 = row0 + wr * 32 + mt * 16 + (lane >> 2);
        int r2 = r1 + 8;
        float dv1 = (r1 < n) ? g_dinv[r1] : 0.f;
        float dv2 = (r2 < n) ? g_dinv[r2] : 0.f;
#pragma unroll
        for (int nt = 0; nt < 8; nt++) {
            int col = wc * 64 + nt * 8 + (lane & 3) * 2;
            if (r1 < n) {
                float2 o = make_float2(acc[mt][nt][0] * dv1, acc[mt][nt][1] * dv1);
                *(float2*)&g_h[r1 * HD + col] = o;
            }
            if (r2 < n) {
                float2 o = make_float2(acc[mt][nt][2] * dv2, acc[mt][nt][3] * dv2);
                *(float2*)&g_h[r2 * HD + col] = o;
            }
        }
    }
}

// ---------------- Aggregation: warp per node, register accumulators (R8-proven) ----------------

__global__ void k_agg(const float* __restrict__ bias, float* __restrict__ out,
                      int out_is_gbuf, int n, int do_relu) {
    int w = (blockIdx.x * blockDim.x + threadIdx.x) >> 5;
    int lane = threadIdx.x & 31;
    if (w >= n) return;

    float* __restrict__ dst = out_is_gbuf ? g_buf : out;

    const float4* hv = (const float4*)g_h;
    float4 a0 = hv[w * 32 + lane];               // self loop
    float4 a1 = make_float4(0.f, 0.f, 0.f, 0.f);
    float4 a2 = make_float4(0.f, 0.f, 0.f, 0.f);
    float4 a3 = make_float4(0.f, 0.f, 0.f, 0.f);

    int beg = g_off[w], end = g_off[w + 1];
    int j = beg;
    for (; j + 3 < end; j += 4) {
        int s0 = g_csr[j], s1 = g_csr[j + 1], s2 = g_csr[j + 2], s3 = g_csr[j + 3];
        float4 m0 = hv[s0 * 32 + lane];
        float4 m1 = hv[s1 * 32 + lane];
        float4 m2 = hv[s2 * 32 + lane];
        float4 m3 = hv[s3 * 32 + lane];
        a0.x += m0.x; a0.y += m0.y; a0.z += m0.z; a0.w += m0.w;
        a1.x += m1.x; a1.y += m1.y; a1.z += m1.z; a1.w += m1.w;
        a2.x += m2.x; a2.y += m2.y; a2.z += m2.z; a2.w += m2.w;
        a3.x += m3.x; a3.y += m3.y; a3.z += m3.z; a3.w += m3.w;
    }
    for (; j < end; j++) {
        float4 m = hv[g_csr[j] * 32 + lane];
        a0.x += m.x; a0.y += m.y; a0.z += m.z; a0.w += m.w;
    }
    float4 acc;
    acc.x = (a0.x + a1.x) + (a2.x + a3.x);
    acc.y = (a0.y + a1.y) + (a2.y + a3.y);
    acc.z = (a0.z + a1.z) + (a2.z + a3.z);
    acc.w = (a0.w + a1.w) + (a2.w + a3.w);

    float dv = g_dinv[w];
    float4 bb = ((const float4*)bias)[lane];
    acc.x = fmaf(acc.x, dv, bb.x);
    acc.y = fmaf(acc.y, dv, bb.y);
    acc.z = fmaf(acc.z, dv, bb.z);
    acc.w = fmaf(acc.w, dv, bb.w);
    if (do_relu) {
        acc.x = fmaxf(acc.x, 0.f); acc.y = fmaxf(acc.y, 0.f);
        acc.z = fmaxf(acc.z, 0.f); acc.w = fmaxf(acc.w, 0.f);
    }
    ((float4*)dst)[w * 32 + lane] = acc;
}

// ---------------- launch ----------------

extern "C" void kernel_launch(void* const* d_in, const int* in_sizes, int n_in,
                              void* d_out, int out_size) {
    const float* x  = (const float*)d_in[0];
    const void*  ei = d_in[1];
    const float* W1 = (const float*)d_in[2];
    const float* b1 = (const float*)d_in[3];
    const float* W2 = (const float*)d_in[4];
    const float* b2 = (const float*)d_in[5];
    const float* W3 = (const float*)d_in[6];
    const float* b3 = (const float*)d_in[7];
    float* out = (float*)d_out;

    int n = in_sizes[0] / HD;     // 50000
    int e = in_sizes[1] / 2;      // 800000

    int nb = (n + 1023) / 1024;
    int e4 = (e + 3) / 4;         // threads for 4-edge-per-thread kernels

    k_init<<<(n + 255) / 256, 256>>>((const int*)ei, n);
    k_hist<<<(e4 + 255) / 256, 256>>>(ei, e, n);
    k_scan1<<<nb, 1024>>>(n);
    k_scan2<<<1, 1024>>>(nb, n);
    k_scan3<<<nb, 1024>>>(n);
    k_scatter<<<(e4 + 255) / 256, 256>>>(ei, e, n);
    k_wsplit<<<192, 256>>>(W1, W2, W3);

    int gemm_blocks = (n + 127) / 128;
    int agg_blocks  = (n * 32 + 255) / 256;

    // layer 1: x -> g_h -> g_buf (relu)
    k_gemm_mma<<<gemm_blocks, 256>>>(x, 0, 0, n);
    k_agg     <<<agg_blocks, 256>>>(b1, nullptr, 1, n, 1);
    // layer 2: g_buf -> g_h -> g_buf (relu)
    k_gemm_mma<<<gemm_blocks, 256>>>(nullptr, 1, 1, n);
    k_agg     <<<agg_blocks, 256>>>(b2, nullptr, 1, n, 1);
    // layer 3: g_buf -> g_h -> out
    k_gemm_mma<<<gemm_blocks, 256>>>(nullptr, 1, 2, n);
    k_agg     <<<agg_blocks, 256>>>(b3, out, 0, n, 0);
}